// round 2
// baseline (speedup 1.0000x reference)
#include <cuda_runtime.h>
#include <cstdint>

// Problem constants
#define NVAR  64
#define HID1  256
#define HID2  128
#define BATCH 16384
#define BT    128                   // batch rows per CTA
#define NCTA  (BATCH / BT)          // 128 CTAs
#define KT1   9                     // L1 K-tiles: K padded 65 -> 72 (u at k=64)
#define CHN   64                    // hidden chunk width (L1 N-chunk == L2 K-chunk)
#define NCH   4                     // HID1 / CHN
#define W1F_CHUNK (8 * KT1 * 64)    // 4608 floats: [nt=8][kt=9][lane=32][2]
#define W2F_CHUNK (16 * 8 * 64)     // 8192 floats: [nt=16][kt=8][lane=32][2]
#define SYS   76                    // SMEM row stride (conflict-free: 12r+c mod 32)

// Scratch (device globals: allocation-free rule)
__device__ float g_W1f[NVAR * NCH * W1F_CHUNK];   // ~4.7 MB, mask+u folded, frag-major, tf32-rounded
__device__ float g_W2f[NVAR * NCH * W2F_CHUNK];   // ~8.4 MB, frag-major, tf32-rounded
__device__ float g_Ut[NVAR * BATCH];              // U transposed

static __device__ __forceinline__ unsigned tf32u(float x) {
    unsigned r;
    asm("cvt.rna.tf32.f32 %0, %1;" : "=r"(r) : "f"(x));
    return r;
}
static __device__ __forceinline__ float tf32f(float x) { return __uint_as_float(tf32u(x)); }

static __device__ __forceinline__ void mma8(float* c,
                                            unsigned a0, unsigned a1, unsigned a2, unsigned a3,
                                            unsigned b0, unsigned b1) {
    asm volatile(
        "mma.sync.aligned.m16n8k8.row.col.f32.tf32.tf32.f32 "
        "{%0,%1,%2,%3},{%4,%5,%6,%7},{%8,%9},{%0,%1,%2,%3};\n"
        : "+f"(c[0]), "+f"(c[1]), "+f"(c[2]), "+f"(c[3])
        : "r"(a0), "r"(a1), "r"(a2), "r"(a3), "r"(b0), "r"(b1));
}

static __device__ __forceinline__ void cp16(float* sdst, const float* gsrc) {
    unsigned sa = (unsigned)__cvta_generic_to_shared(sdst);
    asm volatile("cp.async.cg.shared.global [%0], [%1], 16;\n" :: "r"(sa), "l"(gsrc));
}

// ---------------- prep kernels ----------------
// W1 frag-major, with causal mask folded into rows j<64, u-weights at j=64, zeros j=65..71.
__global__ void sen_prep_w1f(const float* __restrict__ W1, const int* __restrict__ G) {
    int idx = blockIdx.x * blockDim.x + threadIdx.x;
    if (idx >= NVAR * NCH * W1F_CHUNK) return;
    int cidx = idx / W1F_CHUNK;
    int f    = idx - cidx * W1F_CHUNK;
    int v    = cidx / NCH;
    int kc   = cidx - v * NCH;
    int p    = f & 1;
    int lane = (f >> 1) & 31;
    int q    = f >> 6;            // nt*KT1 + kt
    int kt   = q % KT1;
    int nt   = q / KT1;
    int j = kt * 8 + (lane & 3) + 4 * p;       // input-feature (K) index
    int h = kc * CHN + nt * 8 + (lane >> 2);   // hidden (N) index
    float val = 0.f;
    if (j < NVAR) {
        if (G[j * NVAR + v] > 0) val = tf32f(W1[(v * (NVAR + 1) + j) * HID1 + h]);
    } else if (j == NVAR) {
        val = tf32f(W1[(v * (NVAR + 1) + NVAR) * HID1 + h]);  // u weights
    }
    g_W1f[idx] = val;
}

__global__ void sen_prep_w2f(const float* __restrict__ W2) {
    int idx = blockIdx.x * blockDim.x + threadIdx.x;
    if (idx >= NVAR * NCH * W2F_CHUNK) return;
    int cidx = idx / W2F_CHUNK;
    int f    = idx - cidx * W2F_CHUNK;
    int v    = cidx / NCH;
    int kc   = cidx - v * NCH;
    int p    = f & 1;
    int lane = (f >> 1) & 31;
    int q    = f >> 6;            // nt*8 + kt
    int kt   = q & 7;
    int nt   = q >> 3;
    int k = kc * CHN + kt * 8 + (lane & 3) + 4 * p;
    int n = nt * 8 + (lane >> 2);
    g_W2f[idx] = tf32f(W2[(v * HID1 + k) * HID2 + n]);
}

__global__ void sen_prep_ut(const float* __restrict__ U) {
    int idx = blockIdx.x * blockDim.x + threadIdx.x;
    if (idx >= NVAR * BATCH) return;
    int v = idx / BATCH;
    int b = idx - v * BATCH;
    g_Ut[idx] = U[b * NVAR + v];
}

// ---------------- main persistent kernel ----------------
__global__ void __launch_bounds__(256, 1) sen_main(
    const float* __restrict__ X,
    const float* __restrict__ b1g,
    const float* __restrict__ b2g,
    const float* __restrict__ W3g,
    const float* __restrict__ b3g,
    float* __restrict__ out)
{
    extern __shared__ float sm[];
    float* sY  = sm;                          // [128][76]: Y tile, col 64 = u, cols 65..71 = 0
    float* sH  = sY  + BT * SYS;              // [128][76]: h1 chunk (tf32-rounded)
    float* sW1 = sH  + BT * SYS;              // 2 x 4608 (double buffer)
    float* sW2 = sW1 + 2 * W1F_CHUNK;         // 2 x 8192
    float* sB1 = sW2 + 2 * W2F_CHUNK;         // 2 x 256
    float* sB2 = sB1 + 2 * 256;               // 2 x 128
    float* sW3 = sB2 + 2 * 128;               // 2 x 128
    float* sB3 = sW3 + 2 * 128;               // 2

    const int tid  = threadIdx.x;
    const int lane = tid & 31;
    const int w    = tid >> 5;
    const int b0   = blockIdx.x * BT;
    const int rbase = 16 * w + (lane >> 2);   // warp owns rows [16w, 16w+16)

    // init Y tile from X; zero K-pad columns
    for (int idx = tid; idx < BT * 16; idx += 256) {
        int r = idx >> 4, c4 = idx & 15;
        *(float4*)(sY + r * SYS + c4 * 4) = *(const float4*)(X + (b0 + r) * NVAR + c4 * 4);
    }
    for (int idx = tid; idx < BT * 8; idx += 256) {
        int r = idx >> 3, c = 64 + (idx & 7);
        sY[r * SYS + c] = 0.f;
    }

    // prologue: prefetch chunk 0 weights + var-0 biases into buffer 0
    {
        const float* s1 = g_W1f;
        for (int idx = tid; idx < W1F_CHUNK / 4; idx += 256) cp16(sW1 + idx * 4, s1 + idx * 4);
        const float* s2 = g_W2f;
        for (int idx = tid; idx < W2F_CHUNK / 4; idx += 256) cp16(sW2 + idx * 4, s2 + idx * 4);
        sB1[tid] = __ldg(b1g + tid);
        if (tid < 128) { sB2[tid] = __ldg(b2g + tid); sW3[tid] = __ldg(W3g + tid); }
        if (tid == 0) sB3[0] = __ldg(b3g);
        asm volatile("cp.async.commit_group;\n" ::: "memory");
    }

    float acc2[64];  // L2 accumulators: 16 n-tiles x 4 regs (16 rows x 128 cols per warp)
    #pragma unroll
    for (int q = 0; q < 64; ++q) acc2[q] = 0.f;

    #pragma unroll 1
    for (int i = 0; i < NVAR; ++i) {
        const int pb = i & 1;
        // stage this variable's u into column 64 of OWN rows (no cross-warp dep)
        if (lane < 16) sY[(16 * w + lane) * SYS + 64] = g_Ut[i * BATCH + b0 + 16 * w + lane];
        __syncwarp();

        #pragma unroll 1
        for (int kc = 0; kc < NCH; ++kc) {
            const int c   = i * NCH + kc;
            const int cur = c & 1;
            __syncthreads();   // everyone done reading buffer (cur^1) from previous chunk

            // prefetch next chunk into the other buffer
            if (c + 1 < NVAR * NCH) {
                const int nxt = cur ^ 1;
                const float* s1 = g_W1f + (size_t)(c + 1) * W1F_CHUNK;
                float* d1 = sW1 + nxt * W1F_CHUNK;
                for (int idx = tid; idx < W1F_CHUNK / 4; idx += 256) cp16(d1 + idx * 4, s1 + idx * 4);
                const float* s2 = g_W2f + (size_t)(c + 1) * W2F_CHUNK;
                float* d2 = sW2 + nxt * W2F_CHUNK;
                for (int idx = tid; idx < W2F_CHUNK / 4; idx += 256) cp16(d2 + idx * 4, s2 + idx * 4);
                if (kc == 3) {   // next variable's biases (other parity buffer)
                    const int ip = i + 1, qb = pb ^ 1;
                    sB1[qb * 256 + tid] = __ldg(b1g + ip * HID1 + tid);
                    if (tid < 128) {
                        sB2[qb * 128 + tid] = __ldg(b2g + ip * HID2 + tid);
                        sW3[qb * 128 + tid] = __ldg(W3g + ip * HID2 + tid);
                    }
                    if (tid == 0) sB3[qb] = __ldg(b3g + ip);
                }
            }
            asm volatile("cp.async.commit_group;\n" ::: "memory");
            asm volatile("cp.async.wait_group 1;\n" ::: "memory");
            __syncthreads();   // buffer `cur` fully landed for all threads

            // ---- Layer 1: h1[:, kc*64 .. +64) = relu(inp @ W1m + b1), K = 72 (incl. u) ----
            float c1[8][4];
            #pragma unroll
            for (int nt = 0; nt < 8; ++nt) { c1[nt][0] = 0.f; c1[nt][1] = 0.f; c1[nt][2] = 0.f; c1[nt][3] = 0.f; }
            const float* wb1 = sW1 + cur * W1F_CHUNK + lane * 2;
            #pragma unroll
            for (int kt = 0; kt < KT1; ++kt) {
                const int cc = kt * 8 + (lane & 3);
                unsigned a0 = tf32u(sY[rbase * SYS + cc]);
                unsigned a1 = tf32u(sY[(rbase + 8) * SYS + cc]);
                unsigned a2 = tf32u(sY[rbase * SYS + cc + 4]);
                unsigned a3 = tf32u(sY[(rbase + 8) * SYS + cc + 4]);
                #pragma unroll
                for (int nt = 0; nt < 8; ++nt) {
                    float2 bb = *(const float2*)(wb1 + (nt * KT1 + kt) * 64);
                    mma8(c1[nt], a0, a1, a2, a3, __float_as_uint(bb.x), __float_as_uint(bb.y));
                }
            }
            // epilogue: +bias, relu, round to tf32, store h chunk
            {
                const float* B1 = sB1 + pb * 256 + kc * CHN;
                #pragma unroll
                for (int nt = 0; nt < 8; ++nt) {
                    const int col = nt * 8 + (lane & 3) * 2;
                    float bi0 = B1[col], bi1 = B1[col + 1];
                    float v0 = fmaxf(c1[nt][0] + bi0, 0.f);
                    float v1 = fmaxf(c1[nt][1] + bi1, 0.f);
                    float v2 = fmaxf(c1[nt][2] + bi0, 0.f);
                    float v3 = fmaxf(c1[nt][3] + bi1, 0.f);
                    *(float2*)(sH + rbase * SYS + col)       = make_float2(tf32f(v0), tf32f(v1));
                    *(float2*)(sH + (rbase + 8) * SYS + col) = make_float2(tf32f(v2), tf32f(v3));
                }
            }
            __syncthreads();

            // ---- Layer 2 partial: acc2 += h_chunk @ W2[kc*64.. , :] ----
            const float* wb2 = sW2 + cur * W2F_CHUNK + lane * 2;
            #pragma unroll
            for (int kt = 0; kt < 8; ++kt) {
                const int cc = kt * 8 + (lane & 3);
                unsigned a0 = __float_as_uint(sH[rbase * SYS + cc]);
                unsigned a1 = __float_as_uint(sH[(rbase + 8) * SYS + cc]);
                unsigned a2 = __float_as_uint(sH[rbase * SYS + cc + 4]);
                unsigned a3 = __float_as_uint(sH[(rbase + 8) * SYS + cc + 4]);
                #pragma unroll
                for (int nt = 0; nt < 16; ++nt) {
                    float2 bb = *(const float2*)(wb2 + (nt * 8 + kt) * 64);
                    mma8(&acc2[nt * 4], a0, a1, a2, a3, __float_as_uint(bb.x), __float_as_uint(bb.y));
                }
            }
        } // kc

        // ---- Layer 3: y = relu(acc2 + b2) @ w3 + b3; write Y[:, i] (own rows only) ----
        {
            float p0 = 0.f, p1 = 0.f;
            const float* B2 = sB2 + pb * 128;
            const float* w3 = sW3 + pb * 128;
            #pragma unroll
            for (int nt = 0; nt < 16; ++nt) {
                const int col = nt * 8 + (lane & 3) * 2;
                float w30 = w3[col], w31 = w3[col + 1];
                float bb0 = B2[col], bb1 = B2[col + 1];
                p0 += fmaxf(acc2[nt * 4 + 0] + bb0, 0.f) * w30;
                p0 += fmaxf(acc2[nt * 4 + 1] + bb1, 0.f) * w31;
                p1 += fmaxf(acc2[nt * 4 + 2] + bb0, 0.f) * w30;
                p1 += fmaxf(acc2[nt * 4 + 3] + bb1, 0.f) * w31;
                acc2[nt * 4 + 0] = 0.f; acc2[nt * 4 + 1] = 0.f;
                acc2[nt * 4 + 2] = 0.f; acc2[nt * 4 + 3] = 0.f;
            }
            p0 += __shfl_xor_sync(0xffffffffu, p0, 1);
            p0 += __shfl_xor_sync(0xffffffffu, p0, 2);
            p1 += __shfl_xor_sync(0xffffffffu, p1, 1);
            p1 += __shfl_xor_sync(0xffffffffu, p1, 2);
            if ((lane & 3) == 0) {
                float b3v = sB3[pb];
                sY[rbase * SYS + i]       = p0 + b3v;   // full fp32 kept for output
                sY[(rbase + 8) * SYS + i] = p1 + b3v;
            }
            __syncwarp();
        }
    } // i

    __syncthreads();
    for (int idx = tid; idx < BT * 16; idx += 256) {
        int r = idx >> 4, c4 = idx & 15;
        *(float4*)(out + (b0 + r) * NVAR + c4 * 4) = *(const float4*)(sY + r * SYS + c4 * 4);
    }
}

// ---------------- launch ----------------
extern "C" void kernel_launch(void* const* d_in, const int* in_sizes, int n_in,
                              void* d_out, int out_size) {
    (void)in_sizes; (void)n_in; (void)out_size;
    const float* X  = (const float*)d_in[0];
    const float* U  = (const float*)d_in[1];
    const int*   G  = (const int*)  d_in[2];
    const float* W1 = (const float*)d_in[3];
    const float* b1 = (const float*)d_in[4];
    const float* W2 = (const float*)d_in[5];
    const float* b2 = (const float*)d_in[6];
    const float* W3 = (const float*)d_in[7];
    const float* b3 = (const float*)d_in[8];
    float* out = (float*)d_out;

    const int n1 = NVAR * NCH * W1F_CHUNK;
    sen_prep_w1f<<<(n1 + 255) / 256, 256>>>(W1, G);
    const int n2 = NVAR * NCH * W2F_CHUNK;
    sen_prep_w2f<<<(n2 + 255) / 256, 256>>>(W2);
    const int n3 = NVAR * BATCH;
    sen_prep_ut<<<(n3 + 255) / 256, 256>>>(U);

    const size_t smem_floats = (size_t)BT * SYS * 2          // sY + sH
                             + 2 * W1F_CHUNK + 2 * W2F_CHUNK // weight double buffers
                             + 2 * 256 + 2 * 128 + 2 * 128 + 2;
    const size_t smem_bytes = smem_floats * sizeof(float);   // 184,328 B
    cudaFuncSetAttribute(sen_main, cudaFuncAttributeMaxDynamicSharedMemorySize, (int)smem_bytes);
    sen_main<<<NCTA, 256, smem_bytes>>>(X, b1, b2, W3, b3, out);
}

// round 3
// speedup vs baseline: 1.0002x; 1.0002x over previous
#include <cuda_runtime.h>
#include <cstdint>

// Problem constants
#define NVAR  64
#define HID1  256
#define HID2  128
#define BATCH 16384
#define BT    128                   // batch rows per CTA
#define NCTA  (BATCH / BT)          // 128 CTAs
#define KT1   9                     // L1 K-tiles: K padded 65 -> 72 (u at k=64)
#define CHN   64                    // hidden chunk width (L1 N-chunk == L2 K-chunk)
#define NCH   4                     // HID1 / CHN
#define W1F_CHUNK (8 * KT1 * 64)    // 4608 floats: [nt=8][kt=9][lane=32][2]
#define W2F_CHUNK (16 * 8 * 64)     // 8192 floats: [nt=16][kt=8][lane=32][2]
#define SYS   76                    // SMEM row stride (conflict-free: 12r+c mod 32)

// Scratch (device globals: allocation-free rule)
__device__ float g_W1f[NVAR * NCH * W1F_CHUNK];   // ~4.7 MB, mask+u folded, frag-major, tf32-rounded
__device__ float g_W2f[NVAR * NCH * W2F_CHUNK];   // ~8.4 MB, frag-major, tf32-rounded
__device__ float g_Ut[NVAR * BATCH];              // U transposed

static __device__ __forceinline__ unsigned tf32u(float x) {
    unsigned r;
    asm("cvt.rna.tf32.f32 %0, %1;" : "=r"(r) : "f"(x));
    return r;
}
static __device__ __forceinline__ float tf32f(float x) { return __uint_as_float(tf32u(x)); }

static __device__ __forceinline__ void mma8(float* c,
                                            unsigned a0, unsigned a1, unsigned a2, unsigned a3,
                                            unsigned b0, unsigned b1) {
    asm volatile(
        "mma.sync.aligned.m16n8k8.row.col.f32.tf32.tf32.f32 "
        "{%0,%1,%2,%3},{%4,%5,%6,%7},{%8,%9},{%0,%1,%2,%3};\n"
        : "+f"(c[0]), "+f"(c[1]), "+f"(c[2]), "+f"(c[3])
        : "r"(a0), "r"(a1), "r"(a2), "r"(a3), "r"(b0), "r"(b1));
}

static __device__ __forceinline__ void cp16(float* sdst, const float* gsrc) {
    unsigned sa = (unsigned)__cvta_generic_to_shared(sdst);
    asm volatile("cp.async.cg.shared.global [%0], [%1], 16;\n" :: "r"(sa), "l"(gsrc));
}

// ---------------- prep kernels ----------------
// W1 frag-major, with causal mask folded into rows j<64, u-weights at j=64, zeros j=65..71.
__global__ void sen_prep_w1f(const float* __restrict__ W1, const int* __restrict__ G) {
    int idx = blockIdx.x * blockDim.x + threadIdx.x;
    if (idx >= NVAR * NCH * W1F_CHUNK) return;
    int cidx = idx / W1F_CHUNK;
    int f    = idx - cidx * W1F_CHUNK;
    int v    = cidx / NCH;
    int kc   = cidx - v * NCH;
    int p    = f & 1;
    int lane = (f >> 1) & 31;
    int q    = f >> 6;            // nt*KT1 + kt
    int kt   = q % KT1;
    int nt   = q / KT1;
    int j = kt * 8 + (lane & 3) + 4 * p;       // input-feature (K) index
    int h = kc * CHN + nt * 8 + (lane >> 2);   // hidden (N) index
    float val = 0.f;
    if (j < NVAR) {
        if (G[j * NVAR + v] > 0) val = tf32f(W1[(v * (NVAR + 1) + j) * HID1 + h]);
    } else if (j == NVAR) {
        val = tf32f(W1[(v * (NVAR + 1) + NVAR) * HID1 + h]);  // u weights
    }
    g_W1f[idx] = val;
}

__global__ void sen_prep_w2f(const float* __restrict__ W2) {
    int idx = blockIdx.x * blockDim.x + threadIdx.x;
    if (idx >= NVAR * NCH * W2F_CHUNK) return;
    int cidx = idx / W2F_CHUNK;
    int f    = idx - cidx * W2F_CHUNK;
    int v    = cidx / NCH;
    int kc   = cidx - v * NCH;
    int p    = f & 1;
    int lane = (f >> 1) & 31;
    int q    = f >> 6;            // nt*8 + kt
    int kt   = q & 7;
    int nt   = q >> 3;
    int k = kc * CHN + kt * 8 + (lane & 3) + 4 * p;
    int n = nt * 8 + (lane >> 2);
    g_W2f[idx] = tf32f(W2[(v * HID1 + k) * HID2 + n]);
}

__global__ void sen_prep_ut(const float* __restrict__ U) {
    int idx = blockIdx.x * blockDim.x + threadIdx.x;
    if (idx >= NVAR * BATCH) return;
    int v = idx / BATCH;
    int b = idx - v * BATCH;
    g_Ut[idx] = U[b * NVAR + v];
}

// ---------------- main persistent kernel ----------------
__global__ void __launch_bounds__(256, 1) sen_main(
    const float* __restrict__ X,
    const float* __restrict__ b1g,
    const float* __restrict__ b2g,
    const float* __restrict__ W3g,
    const float* __restrict__ b3g,
    float* __restrict__ out)
{
    extern __shared__ float sm[];
    float* sY  = sm;                          // [128][76]: Y tile, col 64 = u, cols 65..71 = 0
    float* sH  = sY  + BT * SYS;              // [128][76]: h1 chunk (tf32-rounded)
    float* sW1 = sH  + BT * SYS;              // 2 x 4608 (double buffer)
    float* sW2 = sW1 + 2 * W1F_CHUNK;         // 2 x 8192
    float* sB1 = sW2 + 2 * W2F_CHUNK;         // 2 x 256
    float* sB2 = sB1 + 2 * 256;               // 2 x 128
    float* sW3 = sB2 + 2 * 128;               // 2 x 128
    float* sB3 = sW3 + 2 * 128;               // 2

    const int tid  = threadIdx.x;
    const int lane = tid & 31;
    const int w    = tid >> 5;
    const int b0   = blockIdx.x * BT;
    const int rbase = 16 * w + (lane >> 2);   // warp owns rows [16w, 16w+16)

    // init Y tile from X; zero K-pad columns
    for (int idx = tid; idx < BT * 16; idx += 256) {
        int r = idx >> 4, c4 = idx & 15;
        *(float4*)(sY + r * SYS + c4 * 4) = *(const float4*)(X + (b0 + r) * NVAR + c4 * 4);
    }
    for (int idx = tid; idx < BT * 8; idx += 256) {
        int r = idx >> 3, c = 64 + (idx & 7);
        sY[r * SYS + c] = 0.f;
    }

    // prologue: prefetch chunk 0 weights + var-0 biases into buffer 0
    {
        const float* s1 = g_W1f;
        for (int idx = tid; idx < W1F_CHUNK / 4; idx += 256) cp16(sW1 + idx * 4, s1 + idx * 4);
        const float* s2 = g_W2f;
        for (int idx = tid; idx < W2F_CHUNK / 4; idx += 256) cp16(sW2 + idx * 4, s2 + idx * 4);
        sB1[tid] = __ldg(b1g + tid);
        if (tid < 128) { sB2[tid] = __ldg(b2g + tid); sW3[tid] = __ldg(W3g + tid); }
        if (tid == 0) sB3[0] = __ldg(b3g);
        asm volatile("cp.async.commit_group;\n" ::: "memory");
    }

    float acc2[64];  // L2 accumulators: 16 n-tiles x 4 regs (16 rows x 128 cols per warp)
    #pragma unroll
    for (int q = 0; q < 64; ++q) acc2[q] = 0.f;

    #pragma unroll 1
    for (int i = 0; i < NVAR; ++i) {
        const int pb = i & 1;
        // stage this variable's u into column 64 of OWN rows (no cross-warp dep)
        if (lane < 16) sY[(16 * w + lane) * SYS + 64] = g_Ut[i * BATCH + b0 + 16 * w + lane];
        __syncwarp();

        #pragma unroll 1
        for (int kc = 0; kc < NCH; ++kc) {
            const int c   = i * NCH + kc;
            const int cur = c & 1;
            __syncthreads();   // everyone done reading buffer (cur^1) from previous chunk

            // prefetch next chunk into the other buffer
            if (c + 1 < NVAR * NCH) {
                const int nxt = cur ^ 1;
                const float* s1 = g_W1f + (size_t)(c + 1) * W1F_CHUNK;
                float* d1 = sW1 + nxt * W1F_CHUNK;
                for (int idx = tid; idx < W1F_CHUNK / 4; idx += 256) cp16(d1 + idx * 4, s1 + idx * 4);
                const float* s2 = g_W2f + (size_t)(c + 1) * W2F_CHUNK;
                float* d2 = sW2 + nxt * W2F_CHUNK;
                for (int idx = tid; idx < W2F_CHUNK / 4; idx += 256) cp16(d2 + idx * 4, s2 + idx * 4);
                if (kc == 3) {   // next variable's biases (other parity buffer)
                    const int ip = i + 1, qb = pb ^ 1;
                    sB1[qb * 256 + tid] = __ldg(b1g + ip * HID1 + tid);
                    if (tid < 128) {
                        sB2[qb * 128 + tid] = __ldg(b2g + ip * HID2 + tid);
                        sW3[qb * 128 + tid] = __ldg(W3g + ip * HID2 + tid);
                    }
                    if (tid == 0) sB3[qb] = __ldg(b3g + ip);
                }
            }
            asm volatile("cp.async.commit_group;\n" ::: "memory");
            asm volatile("cp.async.wait_group 1;\n" ::: "memory");
            __syncthreads();   // buffer `cur` fully landed for all threads

            // ---- Layer 1: h1[:, kc*64 .. +64) = relu(inp @ W1m + b1), K = 72 (incl. u) ----
            float c1[8][4];
            #pragma unroll
            for (int nt = 0; nt < 8; ++nt) { c1[nt][0] = 0.f; c1[nt][1] = 0.f; c1[nt][2] = 0.f; c1[nt][3] = 0.f; }
            const float* wb1 = sW1 + cur * W1F_CHUNK + lane * 2;
            #pragma unroll
            for (int kt = 0; kt < KT1; ++kt) {
                const int cc = kt * 8 + (lane & 3);
                unsigned a0 = tf32u(sY[rbase * SYS + cc]);
                unsigned a1 = tf32u(sY[(rbase + 8) * SYS + cc]);
                unsigned a2 = tf32u(sY[rbase * SYS + cc + 4]);
                unsigned a3 = tf32u(sY[(rbase + 8) * SYS + cc + 4]);
                #pragma unroll
                for (int nt = 0; nt < 8; ++nt) {
                    float2 bb = *(const float2*)(wb1 + (nt * KT1 + kt) * 64);
                    mma8(c1[nt], a0, a1, a2, a3, __float_as_uint(bb.x), __float_as_uint(bb.y));
                }
            }
            // epilogue: +bias, relu, round to tf32, store h chunk
            {
                const float* B1 = sB1 + pb * 256 + kc * CHN;
                #pragma unroll
                for (int nt = 0; nt < 8; ++nt) {
                    const int col = nt * 8 + (lane & 3) * 2;
                    float bi0 = B1[col], bi1 = B1[col + 1];
                    float v0 = fmaxf(c1[nt][0] + bi0, 0.f);
                    float v1 = fmaxf(c1[nt][1] + bi1, 0.f);
                    float v2 = fmaxf(c1[nt][2] + bi0, 0.f);
                    float v3 = fmaxf(c1[nt][3] + bi1, 0.f);
                    *(float2*)(sH + rbase * SYS + col)       = make_float2(tf32f(v0), tf32f(v1));
                    *(float2*)(sH + (rbase + 8) * SYS + col) = make_float2(tf32f(v2), tf32f(v3));
                }
            }
            __syncthreads();

            // ---- Layer 2 partial: acc2 += h_chunk @ W2[kc*64.. , :] ----
            const float* wb2 = sW2 + cur * W2F_CHUNK + lane * 2;
            #pragma unroll
            for (int kt = 0; kt < 8; ++kt) {
                const int cc = kt * 8 + (lane & 3);
                unsigned a0 = __float_as_uint(sH[rbase * SYS + cc]);
                unsigned a1 = __float_as_uint(sH[(rbase + 8) * SYS + cc]);
                unsigned a2 = __float_as_uint(sH[rbase * SYS + cc + 4]);
                unsigned a3 = __float_as_uint(sH[(rbase + 8) * SYS + cc + 4]);
                #pragma unroll
                for (int nt = 0; nt < 16; ++nt) {
                    float2 bb = *(const float2*)(wb2 + (nt * 8 + kt) * 64);
                    mma8(&acc2[nt * 4], a0, a1, a2, a3, __float_as_uint(bb.x), __float_as_uint(bb.y));
                }
            }
        } // kc

        // ---- Layer 3: y = relu(acc2 + b2) @ w3 + b3; write Y[:, i] (own rows only) ----
        {
            float p0 = 0.f, p1 = 0.f;
            const float* B2 = sB2 + pb * 128;
            const float* w3 = sW3 + pb * 128;
            #pragma unroll
            for (int nt = 0; nt < 16; ++nt) {
                const int col = nt * 8 + (lane & 3) * 2;
                float w30 = w3[col], w31 = w3[col + 1];
                float bb0 = B2[col], bb1 = B2[col + 1];
                p0 += fmaxf(acc2[nt * 4 + 0] + bb0, 0.f) * w30;
                p0 += fmaxf(acc2[nt * 4 + 1] + bb1, 0.f) * w31;
                p1 += fmaxf(acc2[nt * 4 + 2] + bb0, 0.f) * w30;
                p1 += fmaxf(acc2[nt * 4 + 3] + bb1, 0.f) * w31;
                acc2[nt * 4 + 0] = 0.f; acc2[nt * 4 + 1] = 0.f;
                acc2[nt * 4 + 2] = 0.f; acc2[nt * 4 + 3] = 0.f;
            }
            p0 += __shfl_xor_sync(0xffffffffu, p0, 1);
            p0 += __shfl_xor_sync(0xffffffffu, p0, 2);
            p1 += __shfl_xor_sync(0xffffffffu, p1, 1);
            p1 += __shfl_xor_sync(0xffffffffu, p1, 2);
            if ((lane & 3) == 0) {
                float b3v = sB3[pb];
                sY[rbase * SYS + i]       = p0 + b3v;   // full fp32 kept for output
                sY[(rbase + 8) * SYS + i] = p1 + b3v;
            }
            __syncwarp();
        }
    } // i

    __syncthreads();
    for (int idx = tid; idx < BT * 16; idx += 256) {
        int r = idx >> 4, c4 = idx & 15;
        *(float4*)(out + (b0 + r) * NVAR + c4 * 4) = *(const float4*)(sY + r * SYS + c4 * 4);
    }
}

// ---------------- launch ----------------
extern "C" void kernel_launch(void* const* d_in, const int* in_sizes, int n_in,
                              void* d_out, int out_size) {
    (void)in_sizes; (void)n_in; (void)out_size;
    const float* X  = (const float*)d_in[0];
    const float* U  = (const float*)d_in[1];
    const int*   G  = (const int*)  d_in[2];
    const float* W1 = (const float*)d_in[3];
    const float* b1 = (const float*)d_in[4];
    const float* W2 = (const float*)d_in[5];
    const float* b2 = (const float*)d_in[6];
    const float* W3 = (const float*)d_in[7];
    const float* b3 = (const float*)d_in[8];
    float* out = (float*)d_out;

    const int n1 = NVAR * NCH * W1F_CHUNK;
    sen_prep_w1f<<<(n1 + 255) / 256, 256>>>(W1, G);
    const int n2 = NVAR * NCH * W2F_CHUNK;
    sen_prep_w2f<<<(n2 + 255) / 256, 256>>>(W2);
    const int n3 = NVAR * BATCH;
    sen_prep_ut<<<(n3 + 255) / 256, 256>>>(U);

    const size_t smem_floats = (size_t)BT * SYS * 2          // sY + sH
                             + 2 * W1F_CHUNK + 2 * W2F_CHUNK // weight double buffers
                             + 2 * 256 + 2 * 128 + 2 * 128 + 2;
    const size_t smem_bytes = smem_floats * sizeof(float);   // 184,328 B
    cudaFuncSetAttribute(sen_main, cudaFuncAttributeMaxDynamicSharedMemorySize, (int)smem_bytes);
    sen_main<<<NCTA, 256, smem_bytes>>>(X, b1, b2, W3, b3, out);
}

// round 5
// speedup vs baseline: 1.7932x; 1.7929x over previous
#include <cuda_runtime.h>
#include <cuda_fp16.h>
#include <cstdint>

// ---------------- constants ----------------
#define NVAR   64
#define HID1   256
#define HID2   128
#define BATCH  16384
#define BT     128
#define NCTA   (BATCH / BT)
#define NCHUNK 256                // 64 vars x 4 quarters
#define W1H    5120               // halfs per W1 chunk: [n8=8][kt=5][lane=32][4 halfs]
#define W2H    8192               // halfs per W2 chunk: [n8=16][kt=4][lane=32][4 halfs]
#define YHS    88                 // sYh row stride in halfs (conflict-free: 44 words, r*12 mod 32)
#define HS     72                 // sH  row stride in halfs (36 words, r*4 mod 32)

// SMEM byte offsets
#define OFF_YH 0                          // 128 x 88 halfs       = 22528
#define OFF_H  22528                      // 128 x 72 halfs       = 18432
#define OFF_W1 40960                      // 2 x 10240            = 20480
#define OFF_W2 61440                      // 2 x 16384            = 32768
#define OFF_YO 94208                      // 128 x 64 fp32        = 32768
#define OFF_B1 126976                     // 2 x 256 f
#define OFF_B2 129024                     // 2 x 128 f
#define OFF_W3 130048                     // 2 x 128 f
#define OFF_B3 131072                     // 2 f
#define OFF_SP 131088                     // 128 f
#define SMEM_TOTAL (OFF_SP + 512)         // 131600 B

// ---------------- device scratch (no allocs allowed) ----------------
__device__ __half g_W1h[NCHUNK * W1H];    // 2.6 MB: mask+u folded, frag-major fp16
__device__ __half g_W2h[NCHUNK * W2H];    // 4.2 MB: frag-major fp16
__device__ __half g_Uth[NVAR * BATCH];    // 2.1 MB: U transposed, fp16

// ---------------- helpers ----------------
static __device__ __forceinline__ void mma16(float* c, const unsigned* a,
                                             unsigned b0, unsigned b1) {
    asm volatile(
        "mma.sync.aligned.m16n8k16.row.col.f32.f16.f16.f32 "
        "{%0,%1,%2,%3},{%4,%5,%6,%7},{%8,%9},{%0,%1,%2,%3};\n"
        : "+f"(c[0]), "+f"(c[1]), "+f"(c[2]), "+f"(c[3])
        : "r"(a[0]), "r"(a[1]), "r"(a[2]), "r"(a[3]), "r"(b0), "r"(b1));
}

static __device__ __forceinline__ void cp16(void* sdst, const void* gsrc) {
    unsigned sa = (unsigned)__cvta_generic_to_shared(sdst);
    asm volatile("cp.async.cg.shared.global [%0], [%1], 16;\n" :: "r"(sa), "l"(gsrc));
}

// ---------------- prep kernels ----------------
// W1 frag-major fp16. Chunk t = i*4+q covers hidden cols [q*64, q*64+64), K padded 65->80.
// flat within chunk: (((n8*5)+kt)*32 + lane)*4 + p*2 + e
//   k = kt*16 + (lane&3)*2 + 8p + e   (b0: k..k+1, b1: k+8..k+9)
//   n = q*64 + n8*8 + (lane>>2)
// mask folded: k<64 kept iff G[k][i]>0; k==64 = u weights; k>64 zero.
__global__ void sen_prep_w1h(const float* __restrict__ W1, const int* __restrict__ G) {
    int idx = blockIdx.x * blockDim.x + threadIdx.x;
    if (idx >= NCHUNK * W1H) return;
    int t    = idx / W1H;
    int rem  = idx - t * W1H;
    int n8   = rem / 640;
    int rem2 = rem - n8 * 640;
    int kt   = rem2 / 128;
    int f    = rem2 - kt * 128;
    int lane = f >> 2, p = (f >> 1) & 1, e = f & 1;
    int i = t >> 2, q = t & 3;
    int k = kt * 16 + (lane & 3) * 2 + 8 * p + e;
    int n = q * 64 + n8 * 8 + (lane >> 2);
    float val = 0.f;
    if (k < NVAR) {
        if (G[k * NVAR + i] > 0) val = W1[(i * (NVAR + 1) + k) * HID1 + n];
    } else if (k == NVAR) {
        val = W1[(i * (NVAR + 1) + NVAR) * HID1 + n];
    }
    g_W1h[idx] = __float2half_rn(val);
}

// W2 frag-major fp16. Chunk t covers K rows [q*64, q*64+64) of W2, all 128 N cols.
//   k = q*64 + kt*16 + (lane&3)*2 + 8p + e ;  n = n8*8 + (lane>>2)
__global__ void sen_prep_w2h(const float* __restrict__ W2) {
    int idx = blockIdx.x * blockDim.x + threadIdx.x;
    if (idx >= NCHUNK * W2H) return;
    int t    = idx / W2H;
    int rem  = idx - t * W2H;
    int n8   = rem / 512;
    int rem2 = rem - n8 * 512;
    int kt   = rem2 / 128;
    int f    = rem2 - kt * 128;
    int lane = f >> 2, p = (f >> 1) & 1, e = f & 1;
    int i = t >> 2, q = t & 3;
    int k = q * 64 + kt * 16 + (lane & 3) * 2 + 8 * p + e;
    int n = n8 * 8 + (lane >> 2);
    g_W2h[idx] = __float2half_rn(W2[(i * HID1 + k) * HID2 + n]);
}

__global__ void sen_prep_ut(const float* __restrict__ U) {
    int idx = blockIdx.x * blockDim.x + threadIdx.x;
    if (idx >= NVAR * BATCH) return;
    int v = idx / BATCH;
    int b = idx - v * BATCH;
    g_Uth[idx] = __float2half_rn(U[b * NVAR + v]);
}

// ---------------- main kernel ----------------
__global__ void __launch_bounds__(256, 1) sen_main(
    const float* __restrict__ X,
    const float* __restrict__ b1g,
    const float* __restrict__ b2g,
    const float* __restrict__ W3g,
    const float* __restrict__ b3g,
    float* __restrict__ out)
{
    extern __shared__ char smem[];
    __half* sYh  = (__half*)(smem + OFF_YH);
    __half* sH   = (__half*)(smem + OFF_H);
    float*  sYo  = (float*)(smem + OFF_YO);
    float*  sB1  = (float*)(smem + OFF_B1);
    float*  sB2  = (float*)(smem + OFF_B2);
    float*  sW3  = (float*)(smem + OFF_W3);
    float*  sB3  = (float*)(smem + OFF_B3);
    float*  sP   = (float*)(smem + OFF_SP);

    const int tid  = threadIdx.x;
    const int lane = tid & 31;
    const int w    = tid >> 5;
    const int wm   = w >> 1;            // M group 0..3 (rows 32*wm .. +32)
    const int wn   = w & 1;             // N group 0..1
    const int b0   = blockIdx.x * BT;
    const int r0   = 32 * wm + (lane >> 2);
    const int ccol = (lane & 3) * 2;

    // ---- init sYh: X cols 0..63 (fp16), cols 64..87 zero (u0 staged below) ----
    for (int idx = tid; idx < BT * 64; idx += 256) {
        int r = idx >> 6, c = idx & 63;
        sYh[r * YHS + c] = __float2half_rn(X[(size_t)(b0 + r) * NVAR + c]);
    }
    for (int idx = tid; idx < BT * 24; idx += 256) {
        int r = idx / 24, c = 64 + (idx - r * 24);
        sYh[r * YHS + c] = __half(0.f);
    }
    if (tid < BT) sYh[tid * YHS + 64] = g_Uth[b0 + tid];   // u for var 0

    // ---- biases for var 0 (parity buffer 0) ----
    sB1[tid] = __ldg(b1g + tid);
    if (tid < 128) { sB2[tid] = __ldg(b2g + tid); sW3[tid] = __ldg(W3g + tid); }
    if (tid == 0) sB3[0] = __ldg(b3g);

    // ---- prologue: prefetch chunk 0 into buffer 0 ----
    {
        char* d1 = smem + OFF_W1;
        for (int idx = tid; idx < W1H / 8; idx += 256)
            cp16(d1 + idx * 16, (const char*)g_W1h + idx * 16);
        char* d2 = smem + OFF_W2;
        for (int idx = tid; idx < W2H / 8; idx += 256)
            cp16(d2 + idx * 16, (const char*)g_W2h + idx * 16);
        asm volatile("cp.async.commit_group;\n" ::: "memory");
    }

    float acc2[2][8][4];
    #pragma unroll
    for (int m = 0; m < 2; ++m)
        #pragma unroll
        for (int n = 0; n < 8; ++n)
            #pragma unroll
            for (int e = 0; e < 4; ++e) acc2[m][n][e] = 0.f;

    #pragma unroll 1
    for (int i = 0; i < NVAR; ++i) {
        const int pb = i & 1;
        #pragma unroll 1
        for (int q = 0; q < 4; ++q) {
            const int t = i * 4 + q;
            __syncthreads();   // prev chunk reads done; y/u writes visible

            // prefetch chunk t+1 into other buffer
            if (t + 1 < NCHUNK) {
                char* d1 = smem + OFF_W1 + ((t + 1) & 1) * (W1H * 2);
                const char* s1 = (const char*)(g_W1h + (size_t)(t + 1) * W1H);
                for (int idx = tid; idx < W1H / 8; idx += 256)
                    cp16(d1 + idx * 16, s1 + idx * 16);
                char* d2 = smem + OFF_W2 + ((t + 1) & 1) * (W2H * 2);
                const char* s2 = (const char*)(g_W2h + (size_t)(t + 1) * W2H);
                for (int idx = tid; idx < W2H / 8; idx += 256)
                    cp16(d2 + idx * 16, s2 + idx * 16);
            }
            // stage next var's biases during q0
            if (q == 0 && i + 1 < NVAR) {
                const int nb = (i + 1) & 1;
                sB1[nb * 256 + tid] = __ldg(b1g + (i + 1) * HID1 + tid);
                if (tid < 128) {
                    sB2[nb * 128 + tid] = __ldg(b2g + (i + 1) * HID2 + tid);
                    sW3[nb * 128 + tid] = __ldg(W3g + (i + 1) * HID2 + tid);
                }
                if (tid == 0) sB3[nb] = __ldg(b3g + i + 1);
            }
            asm volatile("cp.async.commit_group;\n" ::: "memory");
            asm volatile("cp.async.wait_group 1;\n" ::: "memory");  // chunk t landed
            __syncthreads();

            // ---- Layer 1: c1 = inp(K=80 padded) @ W1chunk(64 cols), warp tile 32Mx32N ----
            float c1[2][4][4];
            #pragma unroll
            for (int m = 0; m < 2; ++m)
                #pragma unroll
                for (int n = 0; n < 4; ++n)
                    #pragma unroll
                    for (int e = 0; e < 4; ++e) c1[m][n][e] = 0.f;

            const char* wb1 = smem + OFF_W1 + (t & 1) * (W1H * 2);
            #pragma unroll
            for (int kt = 0; kt < 5; ++kt) {
                unsigned a[2][4];
                #pragma unroll
                for (int Mt = 0; Mt < 2; ++Mt) {
                    const __half* ap = sYh + (r0 + 16 * Mt) * YHS + kt * 16 + ccol;
                    a[Mt][0] = *(const unsigned*)(ap);
                    a[Mt][1] = *(const unsigned*)(ap + 8 * YHS);
                    a[Mt][2] = *(const unsigned*)(ap + 8);
                    a[Mt][3] = *(const unsigned*)(ap + 8 * YHS + 8);
                }
                #pragma unroll
                for (int nt = 0; nt < 4; ++nt) {
                    uint2 bb = *(const uint2*)(wb1 +
                        ((((wn * 4 + nt) * 5 + kt) * 32 + lane) << 3));
                    mma16(c1[0][nt], a[0], bb.x, bb.y);
                    mma16(c1[1][nt], a[1], bb.x, bb.y);
                }
            }

            // ---- epilogue: +b1, relu, fp16, store to sH ----
            {
                const float* B1 = sB1 + pb * 256 + q * 64;
                #pragma unroll
                for (int Mt = 0; Mt < 2; ++Mt) {
                    const int rA = r0 + 16 * Mt;
                    #pragma unroll
                    for (int nt = 0; nt < 4; ++nt) {
                        const int c = wn * 32 + nt * 8 + ccol;
                        const float bi0 = B1[c], bi1 = B1[c + 1];
                        __half2 hA = __floats2half2_rn(
                            fmaxf(c1[Mt][nt][0] + bi0, 0.f),
                            fmaxf(c1[Mt][nt][1] + bi1, 0.f));
                        __half2 hB = __floats2half2_rn(
                            fmaxf(c1[Mt][nt][2] + bi0, 0.f),
                            fmaxf(c1[Mt][nt][3] + bi1, 0.f));
                        *(__half2*)(sH + rA * HS + c)       = hA;
                        *(__half2*)(sH + (rA + 8) * HS + c) = hB;
                    }
                }
            }
            __syncthreads();

            // ---- Layer 2 partial: acc2 += sH(64K) @ W2chunk(128 cols), warp tile 32Mx64N ----
            const char* wb2 = smem + OFF_W2 + (t & 1) * (W2H * 2);
            #pragma unroll
            for (int kt = 0; kt < 4; ++kt) {
                unsigned a[2][4];
                #pragma unroll
                for (int Mt = 0; Mt < 2; ++Mt) {
                    const __half* ap = sH + (r0 + 16 * Mt) * HS + kt * 16 + ccol;
                    a[Mt][0] = *(const unsigned*)(ap);
                    a[Mt][1] = *(const unsigned*)(ap + 8 * HS);
                    a[Mt][2] = *(const unsigned*)(ap + 8);
                    a[Mt][3] = *(const unsigned*)(ap + 8 * HS + 8);
                }
                #pragma unroll
                for (int nt = 0; nt < 8; ++nt) {
                    uint2 bb = *(const uint2*)(wb2 +
                        ((((wn * 8 + nt) * 4 + kt) * 32 + lane) << 3));
                    mma16(acc2[0][nt], a[0], bb.x, bb.y);
                    mma16(acc2[1][nt], a[1], bb.x, bb.y);
                }
            }
        } // q

        // ---- Layer 3: y = relu(acc2 + b2) . w3 + b3 ----
        {
            const float* B2  = sB2 + pb * 128;
            const float* W3s = sW3 + pb * 128;
            float yv[2][2];
            #pragma unroll
            for (int Mt = 0; Mt < 2; ++Mt) {
                float pA = 0.f, pB = 0.f;
                #pragma unroll
                for (int nt = 0; nt < 8; ++nt) {
                    const int c = wn * 64 + nt * 8 + ccol;
                    const float w30 = W3s[c], w31 = W3s[c + 1];
                    const float d0 = B2[c], d1 = B2[c + 1];
                    pA = fmaf(fmaxf(acc2[Mt][nt][0] + d0, 0.f), w30, pA);
                    pA = fmaf(fmaxf(acc2[Mt][nt][1] + d1, 0.f), w31, pA);
                    pB = fmaf(fmaxf(acc2[Mt][nt][2] + d0, 0.f), w30, pB);
                    pB = fmaf(fmaxf(acc2[Mt][nt][3] + d1, 0.f), w31, pB);
                    acc2[Mt][nt][0] = 0.f; acc2[Mt][nt][1] = 0.f;
                    acc2[Mt][nt][2] = 0.f; acc2[Mt][nt][3] = 0.f;
                }
                pA += __shfl_xor_sync(0xffffffffu, pA, 1);
                pA += __shfl_xor_sync(0xffffffffu, pA, 2);
                pB += __shfl_xor_sync(0xffffffffu, pB, 1);
                pB += __shfl_xor_sync(0xffffffffu, pB, 2);
                yv[Mt][0] = pA; yv[Mt][1] = pB;
            }
            if (wn == 1 && (lane & 3) == 0) {
                sP[r0]      = yv[0][0];
                sP[r0 + 8]  = yv[0][1];
                sP[r0 + 16] = yv[1][0];
                sP[r0 + 24] = yv[1][1];
            }
            __syncthreads();
            if (wn == 0 && (lane & 3) == 0) {
                const float b3v = sB3[pb];
                #pragma unroll
                for (int s = 0; s < 4; ++s) {
                    const int r = r0 + 8 * s;               // r0, +8, +16, +24
                    const float y = yv[s >> 1][s & 1] + sP[r] + b3v;
                    sYo[r * 64 + i] = y;                     // fp32 output value
                    sYh[r * YHS + i] = __float2half_rn(y);   // fp16 for later vars
                    if (i + 1 < NVAR)
                        sYh[r * YHS + 64] = g_Uth[(size_t)(i + 1) * BATCH + b0 + r];
                }
            }
        }
    } // i

    __syncthreads();
    for (int idx = tid; idx < BT * 16; idx += 256) {
        int r = idx >> 4, c4 = (idx & 15) * 4;
        float4 v = *(const float4*)(sYo + r * 64 + c4);
        *(float4*)(out + (size_t)(b0 + r) * NVAR + c4) = v;
    }
}

// ---------------- launch ----------------
extern "C" void kernel_launch(void* const* d_in, const int* in_sizes, int n_in,
                              void* d_out, int out_size) {
    (void)in_sizes; (void)n_in; (void)out_size;
    const float* X  = (const float*)d_in[0];
    const float* U  = (const float*)d_in[1];
    const int*   G  = (const int*)  d_in[2];
    const float* W1 = (const float*)d_in[3];
    const float* b1 = (const float*)d_in[4];
    const float* W2 = (const float*)d_in[5];
    const float* b2 = (const float*)d_in[6];
    const float* W3 = (const float*)d_in[7];
    const float* b3 = (const float*)d_in[8];
    float* out = (float*)d_out;

    sen_prep_w1h<<<(NCHUNK * W1H + 255) / 256, 256>>>(W1, G);
    sen_prep_w2h<<<(NCHUNK * W2H + 255) / 256, 256>>>(W2);
    sen_prep_ut<<<(NVAR * BATCH + 255) / 256, 256>>>(U);

    cudaFuncSetAttribute(sen_main, cudaFuncAttributeMaxDynamicSharedMemorySize, SMEM_TOTAL);
    sen_main<<<NCTA, 256, SMEM_TOTAL>>>(X, b1, b2, W3, b3, out);
}

// round 6
// speedup vs baseline: 1.8824x; 1.0497x over previous
#include <cuda_runtime.h>
#include <cuda_fp16.h>
#include <cstdint>

// ---------------- constants ----------------
#define NVAR   64
#define HID1   256
#define HID2   128
#define BATCH  16384
#define BT     128
#define NCTA   (BATCH / BT)
#define NCHUNK 256                // 64 vars x 4 quarters
#define W1H    5120               // halfs per W1 chunk: [n4=4][kt=5][lane=32][8 halfs]
#define W2H    8192               // halfs per W2 chunk: [n4=8][kt=4][lane=32][8 halfs]
#define YHS    88                 // sYh row stride in halfs (conflict-free)
#define HS     72                 // sH  row stride in halfs (conflict-free)
#define HBUF   18432              // one sH buffer, bytes (128 x 72 halfs)

// SMEM byte offsets
#define OFF_YH 0                          // 128 x 88 halfs            = 22528
#define OFF_H  22528                      // 2 x 18432                 = 36864
#define OFF_W1 59392                      // 2 x 10240                 = 20480
#define OFF_W2 79872                      // 2 x 16384                 = 32768
#define OFF_YO 112640                     // 128 x 64 fp32             = 32768
#define OFF_B1 145408                     // 2 x 256 f
#define OFF_B2 147456                     // 2 x 128 f
#define OFF_W3 148480                     // 2 x 128 f
#define OFF_B3 149504                     // 2 f (+pad)
#define OFF_SP 149520                     // 128 f
#define SMEM_TOTAL (OFF_SP + 512 + 16)    // 150048 B

// named barrier ids
#define BFULL0 1
#define BFULL1 2
#define BFREE0 3
#define BFREE1 4
#define BPROD  5
#define BCONS  6
#define BRED   7

// ---------------- device scratch (no allocs allowed) ----------------
__device__ __half g_W1h[NCHUNK * W1H];    // mask+u folded, frag-major fp16
__device__ __half g_W2h[NCHUNK * W2H];    // frag-major fp16
__device__ __half g_Uth[NVAR * BATCH];    // U transposed, fp16

// ---------------- helpers ----------------
static __device__ __forceinline__ void mma16(float* c, const unsigned* a,
                                             unsigned b0, unsigned b1) {
    asm volatile(
        "mma.sync.aligned.m16n8k16.row.col.f32.f16.f16.f32 "
        "{%0,%1,%2,%3},{%4,%5,%6,%7},{%8,%9},{%0,%1,%2,%3};\n"
        : "+f"(c[0]), "+f"(c[1]), "+f"(c[2]), "+f"(c[3])
        : "r"(a[0]), "r"(a[1]), "r"(a[2]), "r"(a[3]), "r"(b0), "r"(b1));
}

static __device__ __forceinline__ void ldmA(unsigned* a, uint32_t saddr) {
    asm volatile("ldmatrix.sync.aligned.m8n8.x4.shared.b16 {%0,%1,%2,%3}, [%4];"
        : "=r"(a[0]), "=r"(a[1]), "=r"(a[2]), "=r"(a[3]) : "r"(saddr));
}

static __device__ __forceinline__ void cp16(void* sdst, const void* gsrc) {
    unsigned sa = (unsigned)__cvta_generic_to_shared(sdst);
    asm volatile("cp.async.cg.shared.global [%0], [%1], 16;\n" :: "r"(sa), "l"(gsrc));
}

#define CP_COMMIT() asm volatile("cp.async.commit_group;\n" ::: "memory")
#define CP_WAIT1()  asm volatile("cp.async.wait_group 1;\n" ::: "memory")
#define BAR_SYNC(id, n)   asm volatile("bar.sync %0, %1;"   :: "r"(id), "r"(n) : "memory")
#define BAR_ARRIVE(id, n) asm volatile("bar.arrive %0, %1;" :: "r"(id), "r"(n) : "memory")

// ---------------- prep kernels ----------------
// W1 frag-major fp16, B-fragments PAIRED: [n4=4][kt=5][lane=32][8 halfs].
// halfs h: n8 = 2*n4 + (h>>2); p = (h>>1)&1 (b0/b1); e = h&1.
//   k = kt*16 + (lane&3)*2 + 8p + e ;  n = q*64 + n8*8 + (lane>>2)
// mask folded: k<64 kept iff G[k][i]>0; k==64 = u weights; k>64 zero.
__global__ void sen_prep_w1h(const float* __restrict__ W1, const int* __restrict__ G) {
    int idx = blockIdx.x * blockDim.x + threadIdx.x;
    if (idx >= NCHUNK * W1H) return;
    int t    = idx / W1H;
    int rem  = idx - t * W1H;
    int n4   = rem / 1280;
    int rem2 = rem - n4 * 1280;
    int kt   = rem2 / 256;
    int f    = rem2 - kt * 256;
    int lane = f >> 3, h = f & 7;
    int n8 = 2 * n4 + (h >> 2);
    int p  = (h >> 1) & 1, e = h & 1;
    int i = t >> 2, q = t & 3;
    int k = kt * 16 + (lane & 3) * 2 + 8 * p + e;
    int n = q * 64 + n8 * 8 + (lane >> 2);
    float val = 0.f;
    if (k < NVAR) {
        if (G[k * NVAR + i] > 0) val = W1[(i * (NVAR + 1) + k) * HID1 + n];
    } else if (k == NVAR) {
        val = W1[(i * (NVAR + 1) + NVAR) * HID1 + n];
    }
    g_W1h[idx] = __float2half_rn(val);
}

// W2 frag-major fp16, paired: [n4=8][kt=4][lane=32][8 halfs].
__global__ void sen_prep_w2h(const float* __restrict__ W2) {
    int idx = blockIdx.x * blockDim.x + threadIdx.x;
    if (idx >= NCHUNK * W2H) return;
    int t    = idx / W2H;
    int rem  = idx - t * W2H;
    int n4   = rem / 1024;
    int rem2 = rem - n4 * 1024;
    int kt   = rem2 / 256;
    int f    = rem2 - kt * 256;
    int lane = f >> 3, h = f & 7;
    int n8 = 2 * n4 + (h >> 2);
    int p  = (h >> 1) & 1, e = h & 1;
    int i = t >> 2, q = t & 3;
    int k = q * 64 + kt * 16 + (lane & 3) * 2 + 8 * p + e;
    int n = n8 * 8 + (lane >> 2);
    g_W2h[idx] = __float2half_rn(W2[(i * HID1 + k) * HID2 + n]);
}

__global__ void sen_prep_ut(const float* __restrict__ U) {
    int idx = blockIdx.x * blockDim.x + threadIdx.x;
    if (idx >= NVAR * BATCH) return;
    int v = idx / BATCH;
    int b = idx - v * BATCH;
    g_Uth[idx] = __float2half_rn(U[b * NVAR + v]);
}

// ---------------- main kernel: 512 threads, warp-specialized ----------------
__global__ void __launch_bounds__(512, 1) sen_main(
    const float* __restrict__ X,
    const float* __restrict__ b1g,
    const float* __restrict__ b2g,
    const float* __restrict__ W3g,
    const float* __restrict__ b3g,
    float* __restrict__ out)
{
    extern __shared__ char smem[];
    __half* sYh  = (__half*)(smem + OFF_YH);
    __half* sH   = (__half*)(smem + OFF_H);
    float*  sYo  = (float*)(smem + OFF_YO);
    float*  sB1  = (float*)(smem + OFF_B1);
    float*  sB2  = (float*)(smem + OFF_B2);
    float*  sW3  = (float*)(smem + OFF_W3);
    float*  sB3  = (float*)(smem + OFF_B3);
    float*  sP   = (float*)(smem + OFF_SP);
    const uint32_t smb = (uint32_t)__cvta_generic_to_shared(smem);

    const int tid  = threadIdx.x;
    const int lane = tid & 31;
    const int w    = tid >> 5;
    const bool producer = (w < 8);
    const int wg   = producer ? w : (w - 8);
    const int wm   = wg >> 1;               // M group 0..3
    const int wn   = wg & 1;                // N group 0..1
    const int b0   = blockIdx.x * BT;
    const int r0   = 32 * wm + (lane >> 2);
    const int ccol = (lane & 3) * 2;
    const int tid2 = tid & 255;             // index within role group

    // ldmatrix per-lane base addresses
    const uint32_t aYb = smb + OFF_YH +
        ((((32 * wm + (lane & 15)) * YHS) + (lane >> 4) * 8) << 1);
    const uint32_t aHb = smb + OFF_H +
        ((((32 * wm + (lane & 15)) * HS) + (lane >> 4) * 8) << 1);

    // ---- init sYh: X cols 0..63 fp16, cols 64..87 zero, u0 at col 64 ----
    for (int idx = tid; idx < BT * 64; idx += 512) {
        int r = idx >> 6, c = idx & 63;
        sYh[r * YHS + c] = __float2half_rn(X[(size_t)(b0 + r) * NVAR + c]);
    }
    for (int idx = tid; idx < BT * 24; idx += 512) {
        int r = idx / 24, c = 64 + (idx - r * 24);
        sYh[r * YHS + c] = __half(0.f);
    }
    if (tid < BT) sYh[tid * YHS + 64] = g_Uth[b0 + tid];

    // var-0 biases (parity 0)
    if (tid < 256) sB1[tid] = __ldg(b1g + tid);
    if (tid < 128) { sB2[tid] = __ldg(b2g + tid); sW3[tid] = __ldg(W3g + tid); }
    if (tid == 0) sB3[0] = __ldg(b3g);

    // prologue: producers prefetch W1(0), consumers W2(0)
    if (producer) {
        char* d = smem + OFF_W1;
        for (int idx = tid2; idx < W1H / 8; idx += 256)
            cp16(d + idx * 16, (const char*)g_W1h + idx * 16);
    } else {
        char* d = smem + OFF_W2;
        for (int idx = tid2; idx < W2H / 8; idx += 256)
            cp16(d + idx * 16, (const char*)g_W2h + idx * 16);
    }
    CP_COMMIT();
    __syncthreads();

    float acc2[2][8][4];   // consumer L2 accumulators (dead regs for producers)
    #pragma unroll
    for (int m = 0; m < 2; ++m)
        #pragma unroll
        for (int n = 0; n < 8; ++n)
            #pragma unroll
            for (int e = 0; e < 4; ++e) acc2[m][n][e] = 0.f;

    #pragma unroll 1
    for (int i = 0; i < NVAR; ++i) {
        const int pb = i & 1;

        if (producer) {
            // ================= producer: L1 GEMM chain =================
            #pragma unroll 1
            for (int q = 0; q < 4; ++q) {
                const int t = i * 4 + q;
                const int buf = q & 1;
                BAR_SYNC(BPROD, 256);    // all producers done reading W1 buf[(t+1)&1]'s old content
                if (t + 1 < NCHUNK) {
                    char* d = smem + OFF_W1 + ((t + 1) & 1) * (W1H * 2);
                    const char* s = (const char*)(g_W1h + (size_t)(t + 1) * W1H);
                    for (int idx = tid2; idx < W1H / 8; idx += 256)
                        cp16(d + idx * 16, s + idx * 16);
                }
                CP_COMMIT();
                if (q == 0 && i + 1 < NVAR) {   // stage next var's b1
                    sB1[((i + 1) & 1) * 256 + tid2] = __ldg(b1g + (i + 1) * HID1 + tid2);
                }
                CP_WAIT1();                     // W1(t) landed (own copies)
                BAR_SYNC(BPROD, 256);           // all producers' W1(t) copies visible

                // ---- L1: 128M x 64N x 80K, warp tile 32M x 32N ----
                float c1[2][4][4];
                #pragma unroll
                for (int m = 0; m < 2; ++m)
                    #pragma unroll
                    for (int n = 0; n < 4; ++n)
                        #pragma unroll
                        for (int e = 0; e < 4; ++e) c1[m][n][e] = 0.f;

                const char* wb1 = smem + OFF_W1 + (t & 1) * (W1H * 2);
                #pragma unroll
                for (int kt = 0; kt < 5; ++kt) {
                    unsigned a0[4], a1[4];
                    ldmA(a0, aYb + kt * 32);
                    ldmA(a1, aYb + kt * 32 + 16 * YHS * 2);
                    #pragma unroll
                    for (int n4 = 0; n4 < 2; ++n4) {
                        uint4 bb = *(const uint4*)(wb1 +
                            ((((wn * 2 + n4) * 5 + kt) * 32 + lane) << 4));
                        mma16(c1[0][2 * n4],     a0, bb.x, bb.y);
                        mma16(c1[0][2 * n4 + 1], a0, bb.z, bb.w);
                        mma16(c1[1][2 * n4],     a1, bb.x, bb.y);
                        mma16(c1[1][2 * n4 + 1], a1, bb.z, bb.w);
                    }
                }

                // ---- epilogue: +b1, relu, fp16 -> sH[buf] ----
                if (q >= 2) BAR_SYNC(BFREE0 + buf, 512);   // consumer freed this buffer
                {
                    __half* sHb = (__half*)(smem + OFF_H + buf * HBUF);
                    const float* B1 = sB1 + pb * 256 + q * 64;
                    #pragma unroll
                    for (int Mt = 0; Mt < 2; ++Mt) {
                        const int rA = r0 + 16 * Mt;
                        #pragma unroll
                        for (int nt = 0; nt < 4; ++nt) {
                            const int c = wn * 32 + nt * 8 + ccol;
                            const float bi0 = B1[c], bi1 = B1[c + 1];
                            __half2 hA = __floats2half2_rn(
                                fmaxf(c1[Mt][nt][0] + bi0, 0.f),
                                fmaxf(c1[Mt][nt][1] + bi1, 0.f));
                            __half2 hB = __floats2half2_rn(
                                fmaxf(c1[Mt][nt][2] + bi0, 0.f),
                                fmaxf(c1[Mt][nt][3] + bi1, 0.f));
                            *(__half2*)(sHb + rA * HS + c)       = hA;
                            *(__half2*)(sHb + (rA + 8) * HS + c) = hB;
                        }
                    }
                }
                BAR_ARRIVE(BFULL0 + buf, 512);
            }
        } else {
            // ================= consumer: L2 GEMM + L3 chain =================
            #pragma unroll 1
            for (int q = 0; q < 4; ++q) {
                const int t = i * 4 + q;
                const int buf = q & 1;
                BAR_SYNC(BCONS, 256);
                if (t + 1 < NCHUNK) {
                    char* d = smem + OFF_W2 + ((t + 1) & 1) * (W2H * 2);
                    const char* s = (const char*)(g_W2h + (size_t)(t + 1) * W2H);
                    for (int idx = tid2; idx < W2H / 8; idx += 256)
                        cp16(d + idx * 16, s + idx * 16);
                }
                CP_COMMIT();
                if (q == 0 && i + 1 < NVAR) {   // stage next var's b2/w3/b3
                    const int nb = (i + 1) & 1;
                    if (tid2 < 128) {
                        sB2[nb * 128 + tid2] = __ldg(b2g + (i + 1) * HID2 + tid2);
                        sW3[nb * 128 + tid2] = __ldg(W3g + (i + 1) * HID2 + tid2);
                    }
                    if (tid2 == 0) sB3[nb] = __ldg(b3g + i + 1);
                }
                CP_WAIT1();
                BAR_SYNC(BCONS, 256);           // W2(t) visible to all consumers
                BAR_SYNC(BFULL0 + buf, 512);    // sH[buf] full

                // ---- L2 partial: 128M x 128N x 64K, warp tile 32M x 64N ----
                const char* wb2 = smem + OFF_W2 + (t & 1) * (W2H * 2);
                const uint32_t aH = aHb + buf * HBUF;
                #pragma unroll
                for (int kt = 0; kt < 4; ++kt) {
                    unsigned a0[4], a1[4];
                    ldmA(a0, aH + kt * 32);
                    ldmA(a1, aH + kt * 32 + 16 * HS * 2);
                    #pragma unroll
                    for (int n4 = 0; n4 < 4; ++n4) {
                        uint4 bb = *(const uint4*)(wb2 +
                            ((((wn * 4 + n4) * 4 + kt) * 32 + lane) << 4));
                        mma16(acc2[0][2 * n4],     a0, bb.x, bb.y);
                        mma16(acc2[0][2 * n4 + 1], a0, bb.z, bb.w);
                        mma16(acc2[1][2 * n4],     a1, bb.x, bb.y);
                        mma16(acc2[1][2 * n4 + 1], a1, bb.z, bb.w);
                    }
                }
                if (q < 2) BAR_ARRIVE(BFREE0 + buf, 512);
            }

            // ---- L3: y = relu(acc2 + b2) . w3 + b3 ----
            {
                const float* B2  = sB2 + pb * 128;
                const float* W3s = sW3 + pb * 128;
                float yv[2][2];
                #pragma unroll
                for (int Mt = 0; Mt < 2; ++Mt) {
                    float pA = 0.f, pB = 0.f;
                    #pragma unroll
                    for (int nt = 0; nt < 8; ++nt) {
                        const int c = wn * 64 + nt * 8 + ccol;
                        const float w30 = W3s[c], w31 = W3s[c + 1];
                        const float d0 = B2[c], d1 = B2[c + 1];
                        pA = fmaf(fmaxf(acc2[Mt][nt][0] + d0, 0.f), w30, pA);
                        pA = fmaf(fmaxf(acc2[Mt][nt][1] + d1, 0.f), w31, pA);
                        pB = fmaf(fmaxf(acc2[Mt][nt][2] + d0, 0.f), w30, pB);
                        pB = fmaf(fmaxf(acc2[Mt][nt][3] + d1, 0.f), w31, pB);
                        acc2[Mt][nt][0] = 0.f; acc2[Mt][nt][1] = 0.f;
                        acc2[Mt][nt][2] = 0.f; acc2[Mt][nt][3] = 0.f;
                    }
                    pA += __shfl_xor_sync(0xffffffffu, pA, 1);
                    pA += __shfl_xor_sync(0xffffffffu, pA, 2);
                    pB += __shfl_xor_sync(0xffffffffu, pB, 1);
                    pB += __shfl_xor_sync(0xffffffffu, pB, 2);
                    yv[Mt][0] = pA; yv[Mt][1] = pB;
                }
                if (wn == 1 && (lane & 3) == 0) {
                    sP[r0]      = yv[0][0];
                    sP[r0 + 8]  = yv[0][1];
                    sP[r0 + 16] = yv[1][0];
                    sP[r0 + 24] = yv[1][1];
                }
                BAR_SYNC(BRED, 256);
                if (wn == 0 && (lane & 3) == 0) {
                    const float b3v = sB3[pb];
                    #pragma unroll
                    for (int s = 0; s < 4; ++s) {
                        const int r = r0 + 8 * s;
                        const float y = yv[s >> 1][s & 1] + sP[r] + b3v;
                        sYo[r * 64 + i] = y;                     // fp32 output
                        sYh[r * YHS + i] = __float2half_rn(y);   // fp16 for later vars
                        if (i + 1 < NVAR)
                            sYh[r * YHS + 64] = g_Uth[(size_t)(i + 1) * BATCH + b0 + r];
                    }
                }
            }
        }
        __syncthreads();   // var boundary: y/u visible to producers
    } // i

    for (int idx = tid; idx < BT * 16; idx += 512) {
        int r = idx >> 4, c4 = (idx & 15) * 4;
        float4 v = *(const float4*)(sYo + r * 64 + c4);
        *(float4*)(out + (size_t)(b0 + r) * NVAR + c4) = v;
    }
}

// ---------------- launch ----------------
extern "C" void kernel_launch(void* const* d_in, const int* in_sizes, int n_in,
                              void* d_out, int out_size) {
    (void)in_sizes; (void)n_in; (void)out_size;
    const float* X  = (const float*)d_in[0];
    const float* U  = (const float*)d_in[1];
    const int*   G  = (const int*)  d_in[2];
    const float* W1 = (const float*)d_in[3];
    const float* b1 = (const float*)d_in[4];
    const float* W2 = (const float*)d_in[5];
    const float* b2 = (const float*)d_in[6];
    const float* W3 = (const float*)d_in[7];
    const float* b3 = (const float*)d_in[8];
    float* out = (float*)d_out;

    sen_prep_w1h<<<(NCHUNK * W1H + 255) / 256, 256>>>(W1, G);
    sen_prep_w2h<<<(NCHUNK * W2H + 255) / 256, 256>>>(W2);
    sen_prep_ut<<<(NVAR * BATCH + 255) / 256, 256>>>(U);

    cudaFuncSetAttribute(sen_main, cudaFuncAttributeMaxDynamicSharedMemorySize, SMEM_TOTAL);
    sen_main<<<NCTA, 512, SMEM_TOTAL>>>(X, b1, b2, W3, b3, out);
}